// round 3
// baseline (speedup 1.0000x reference)
#include <cuda_runtime.h>
#include <cuda_bf16.h>
#include <cstdint>

// Problem constants
#define NN   32
#define CC   512
#define HWL  3136        // 56*56
#define GG   8
#define LL   64
#define MTOT 100352      // NN*HWL
#define EPSV 1e-4f
#define NPART 128        // 32 n-chunks * 4 k-chunks

typedef unsigned long long ull;

// ---------------- scratch (device globals; no allocation allowed) -------------
__device__ float g_pcov[GG][NPART][LL * LL];  // partial Grams (16.8 MB)
__device__ float g_psum[GG][NPART][LL];       // partial channel sums
__device__ float g_mu[CC];
__device__ float g_cov[GG * LL * LL];
__device__ float g_subT[GG * LL * LL];        // whitening subspace, TRANSPOSED [g][j][i]
__device__ float g_t[CC];                     // t[c] = sum_j S[c][j] * mu[g*64+j]
__device__ __align__(16) ull g_Sdup[GG][LL][LL];  // lane-duplicated S: [g][k][i] = (S[i][k],S[i][k])

// ---------------- packed f32x2 helpers ----------------------------------------
__device__ __forceinline__ ull ffma2(ull a, ull b, ull c) {
    ull d;
    asm("fma.rn.f32x2 %0, %1, %2, %3;" : "=l"(d) : "l"(a), "l"(b), "l"(c));
    return d;
}
__device__ __forceinline__ float2 unpack2(ull v) {
    unsigned lo, hi;
    asm("mov.b64 {%0, %1}, %2;" : "=r"(lo), "=r"(hi) : "l"(v));
    float2 f;
    f.x = __uint_as_float(lo);
    f.y = __uint_as_float(hi);
    return f;
}

// =============================================================================
// Kernel 1: partial Gram + partial channel sums, packed-f32x2 inner product.
// grid (4 k-chunks, 32 n, 8 g), 256 threads. Symmetric: only upper 4x4 tiles.
// =============================================================================
__global__ __launch_bounds__(256) void k_cov_partial(const float* __restrict__ x) {
    const int q = blockIdx.x;
    const int n = blockIdx.y;
    const int g = blockIdx.z;
    __shared__ float4 Xs[64][17];       // padded; 16B-aligned rows

    const int tid = threadIdx.x;

    int ty = -1, tx = -1;
    if (tid < 136) {
        int t = tid, r = 0;
        while (t >= 16 - r) { t -= 16 - r; ++r; }
        ty = r; tx = r + t;
    }

    const int tiles = (q == 0) ? 13 : 12;
    const int k0    = (q == 0) ? 0 : (832 + (q - 1) * 768);
    const float* base = x + ((size_t)n * CC + (size_t)g * LL) * HWL + k0;

    ull acc2[4][4];
    #pragma unroll
    for (int u = 0; u < 4; ++u)
        #pragma unroll
        for (int w = 0; w < 4; ++w) acc2[u][w] = 0ull;
    float rowsum = 0.f;

    for (int tI = 0; tI < tiles; ++tI) {
        __syncthreads();
        #pragma unroll
        for (int idx = tid; idx < 1024; idx += 256) {
            int r = idx >> 4, c = idx & 15;
            Xs[r][c] = *reinterpret_cast<const float4*>(base + (size_t)r * HWL + tI * 64 + c * 4);
        }
        __syncthreads();

        if (tid < 64) {
            #pragma unroll
            for (int c = 0; c < 16; ++c) {
                float4 v = Xs[tid][c];
                rowsum += v.x + v.y + v.z + v.w;
            }
        }
        if (tid < 136) {
            #pragma unroll
            for (int c = 0; c < 16; ++c) {
                ulonglong2 a[4], b[4];
                #pragma unroll
                for (int u = 0; u < 4; ++u)
                    a[u] = *reinterpret_cast<const ulonglong2*>(&Xs[4 * ty + u][c]);
                #pragma unroll
                for (int u = 0; u < 4; ++u)
                    b[u] = *reinterpret_cast<const ulonglong2*>(&Xs[4 * tx + u][c]);
                #pragma unroll
                for (int u = 0; u < 4; ++u)
                    #pragma unroll
                    for (int w = 0; w < 4; ++w)
                        acc2[u][w] = ffma2(a[u].x, b[w].x, ffma2(a[u].y, b[w].y, acc2[u][w]));
            }
        }
    }

    const int p = n * 4 + q;
    if (tid < 64) g_psum[g][p][tid] = rowsum;
    if (tid < 136) {
        float* out = &g_pcov[g][p][0];
        #pragma unroll
        for (int u = 0; u < 4; ++u)
            #pragma unroll
            for (int w = 0; w < 4; ++w) {
                int i = 4 * ty + u, j = 4 * tx + w;
                float2 f = unpack2(acc2[u][w]);
                float v = f.x + f.y;
                out[i * 64 + j] = v;
                if (ty != tx) out[j * 64 + i] = v;
            }
    }
}

// =============================================================================
// Kernel 2a: reduce channel sums -> mu.  grid 8, 64 threads.
// =============================================================================
__global__ __launch_bounds__(64) void k_mean() {
    const int g = blockIdx.x, i = threadIdx.x;
    float s = 0.f;
    for (int p = 0; p < NPART; ++p) s += g_psum[g][p][i];
    g_mu[g * LL + i] = s / (float)MTOT;
}

// =============================================================================
// Kernel 2b: reduce partial Grams -> cov (with -mu mu^T + eps I). grid (16,8).
// =============================================================================
__global__ __launch_bounds__(256) void k_cov_finalize() {
    const int g = blockIdx.y;
    const int e = blockIdx.x * 256 + threadIdx.x;
    const int i = e >> 6, j = e & 63;
    float s0 = 0.f, s1 = 0.f, s2 = 0.f, s3 = 0.f;
    #pragma unroll 4
    for (int p = 0; p < NPART; p += 4) {
        s0 += g_pcov[g][p + 0][e];
        s1 += g_pcov[g][p + 1][e];
        s2 += g_pcov[g][p + 2][e];
        s3 += g_pcov[g][p + 3][e];
    }
    float c = ((s0 + s1) + (s2 + s3)) / (float)MTOT - g_mu[g * LL + i] * g_mu[g * LL + j];
    if (i == j) c += EPSV;
    g_cov[g * LL * LL + e] = c;
}

// =============================================================================
// Kernel 3: power iteration + deflation (unchanged — matched reference in R1).
// =============================================================================
#define MATVEC64(res, Aarr, vptr) {                                        \
    float y0 = 0.f, y1 = 0.f, y2 = 0.f, y3 = 0.f;                          \
    _Pragma("unroll")                                                      \
    for (int j_ = 0; j_ < 64; j_ += 4) {                                   \
        y0 = fmaf(Aarr[j_ + 0], (vptr)[j_ + 0], y0);                       \
        y1 = fmaf(Aarr[j_ + 1], (vptr)[j_ + 1], y1);                       \
        y2 = fmaf(Aarr[j_ + 2], (vptr)[j_ + 2], y2);                       \
        y3 = fmaf(Aarr[j_ + 3], (vptr)[j_ + 3], y3);                       \
    }                                                                      \
    res = (y0 + y1) + (y2 + y3);                                           \
}

__device__ __forceinline__ float sumsq64(const float* v) {
    float y0 = 0.f, y1 = 0.f, y2 = 0.f, y3 = 0.f;
    #pragma unroll
    for (int j = 0; j < 64; j += 4) {
        y0 = fmaf(v[j + 0], v[j + 0], y0);
        y1 = fmaf(v[j + 1], v[j + 1], y1);
        y2 = fmaf(v[j + 2], v[j + 2], y2);
        y3 = fmaf(v[j + 3], v[j + 3], y3);
    }
    return (y0 + y1) + (y2 + y3);
}
__device__ __forceinline__ float dot64(const float* a, const float* b) {
    float y0 = 0.f, y1 = 0.f, y2 = 0.f, y3 = 0.f;
    #pragma unroll
    for (int j = 0; j < 64; j += 4) {
        y0 = fmaf(a[j + 0], b[j + 0], y0);
        y1 = fmaf(a[j + 1], b[j + 1], y1);
        y2 = fmaf(a[j + 2], b[j + 2], y2);
        y3 = fmaf(a[j + 3], b[j + 3], y3);
    }
    return (y0 + y1) + (y2 + y3);
}

__global__ __launch_bounds__(64) void k_pi(const float* __restrict__ vinit) {
    const int g = blockIdx.x, i = threadIdx.x;
    __shared__ float vs[2][64];
    __shared__ float av[64];

    float A[64], S[64];
    #pragma unroll
    for (int j = 0; j < 64; ++j) {
        A[j] = g_cov[g * LL * LL + i * 64 + j];
        S[j] = 0.f;
    }

    float lam_prev = 0.f;

    for (int e = 0; e < 64; ++e) {
        __syncthreads();
        vs[0][i] = vinit[((size_t)g * LL + e) * LL + i];
        __syncthreads();

        float n2  = sumsq64(vs[0]);
        float inv = 1.f / (sqrtf(n2) + 1e-12f);
        int cur = 0;

        #pragma unroll 1
        for (int it = 0; it < 19; ++it) {
            float y;
            MATVEC64(y, A, vs[cur]);
            y *= inv;
            vs[cur ^ 1][i] = y;
            __syncthreads();
            cur ^= 1;
            n2  = sumsq64(vs[cur]);
            inv = 1.f / (sqrtf(n2) + 1e-12f);
        }

        float vi = vs[cur][i] * inv;
        __syncthreads();
        vs[cur ^ 1][i] = vi;
        __syncthreads();
        cur ^= 1;

        float Avi;
        MATVEC64(Avi, A, vs[cur]);
        av[i] = Avi;
        __syncthreads();

        float vAv = dot64(vs[cur], av);
        float vv  = sumsq64(vs[cur]);
        float lam = vAv / vv;

        if (e > 0 && (lam_prev < lam || lam < EPSV)) break;

        float svi = rsqrtf(lam) * vi;
        #pragma unroll
        for (int j = 0; j < 64; ++j) {
            float vj = vs[cur][j];
            S[j] = fmaf(svi, vj, S[j]);
            A[j] = fmaf(-Avi, vj, A[j]);
        }
        lam_prev = lam;
    }

    #pragma unroll
    for (int j = 0; j < 64; ++j) g_subT[g * LL * LL + j * 64 + i] = S[j];

    float t = 0.f;
    #pragma unroll
    for (int j = 0; j < 64; ++j) t = fmaf(S[j], g_mu[g * LL + j], t);
    g_t[g * LL + i] = t;
}

// =============================================================================
// Kernel 3b: lane-duplicate S into g_Sdup[g][k][i] = (S[i][k], S[i][k]).
// g_subT[g][k*64+i] already holds S[i][k]. grid 8 x 256.
// =============================================================================
__global__ __launch_bounds__(256) void k_prep() {
    const int g = blockIdx.x;
    for (int idx = threadIdx.x; idx < LL * LL; idx += 256) {
        float v = g_subT[g * LL * LL + idx];
        unsigned u = __float_as_uint(v);
        g_Sdup[g][0][idx] = ((ull)u << 32) | (ull)u;
    }
}

// =============================================================================
// Kernel 4: apply whitening + affine with packed f32x2.
// out = (S @ x - t) * weight + bias.
// grid (7 row-chunks, 32 n, 8 g), 256 threads. Each block: 7 tiles of 64 hw.
// Sdup (32KB) loaded once per block; X tile (16KB) per inner tile.
// =============================================================================
#define AP_SMEM_BYTES (32768 + 16384)

__global__ __launch_bounds__(256, 3) void k_apply(const float* __restrict__ x,
                                                  const float* __restrict__ wgt,
                                                  const float* __restrict__ bia,
                                                  float* __restrict__ out) {
    extern __shared__ char smem[];
    ull*    Sd = reinterpret_cast<ull*>(smem);                 // [64][64]
    float4* Xt = reinterpret_cast<float4*>(smem + 32768);      // [64][16] (no pad)

    const int hb = blockIdx.x;     // 0..6, chunk of 448 hw
    const int n  = blockIdx.y;
    const int g  = blockIdx.z;
    const int tid = threadIdx.x;
    const int ty = tid >> 4, tx = tid & 15;

    // load Sdup once (32 KB, coalesced)
    {
        const ull* src = &g_Sdup[g][0][0];
        #pragma unroll
        for (int i = tid; i < 4096; i += 256) Sd[i] = src[i];
    }

    // per-thread epilogue constants (4 output channels)
    float tc[4], wc[4], bc[4];
    #pragma unroll
    for (int u = 0; u < 4; ++u) {
        int c = g * LL + 4 * ty + u;
        tc[u] = g_t[c]; wc[u] = wgt[c]; bc[u] = bia[c];
    }

    const float* xbase = x   + ((size_t)n * CC + (size_t)g * LL) * HWL + hb * 448;
    float*       obase = out + ((size_t)n * CC + (size_t)g * LL) * HWL + hb * 448;

    const int lch = tid >> 4;    // 0..15: load-row base, +16 per i
    const int lq  = tid & 15;    // hw quad

    // prefetch tile 0
    float4 r[4];
    {
        const float* p = xbase + lq * 4;
        #pragma unroll
        for (int i = 0; i < 4; ++i)
            r[i] = *reinterpret_cast<const float4*>(p + (size_t)(lch + 16 * i) * HWL);
    }

    for (int t = 0; t < 7; ++t) {
        // store current tile to shared
        #pragma unroll
        for (int i = 0; i < 4; ++i) Xt[(lch + 16 * i) * 16 + lq] = r[i];
        __syncthreads();

        // prefetch next tile (gmem latency overlaps the FMA loop)
        if (t < 6) {
            const float* p = xbase + (t + 1) * 64 + lq * 4;
            #pragma unroll
            for (int i = 0; i < 4; ++i)
                r[i] = *reinterpret_cast<const float4*>(p + (size_t)(lch + 16 * i) * HWL);
        }

        // packed GEMM: acc[u] over 4 m-values (two f32x2)
        ull acc0[4] = {0ull, 0ull, 0ull, 0ull};
        ull acc1[4] = {0ull, 0ull, 0ull, 0ull};
        #pragma unroll 8
        for (int k = 0; k < 64; ++k) {
            ulonglong2 b = *reinterpret_cast<const ulonglong2*>(&Xt[k * 16 + tx]);
            #pragma unroll
            for (int u = 0; u < 4; ++u) {
                ull a = Sd[k * 64 + 4 * ty + u];
                acc0[u] = ffma2(a, b.x, acc0[u]);
                acc1[u] = ffma2(a, b.y, acc1[u]);
            }
        }

        // epilogue: (acc - t) * w + b, direct float4 stores
        float* op = obase + t * 64 + 4 * tx;
        #pragma unroll
        for (int u = 0; u < 4; ++u) {
            float2 f01 = unpack2(acc0[u]);
            float2 f23 = unpack2(acc1[u]);
            float4 v;
            v.x = fmaf(f01.x - tc[u], wc[u], bc[u]);
            v.y = fmaf(f01.y - tc[u], wc[u], bc[u]);
            v.z = fmaf(f23.x - tc[u], wc[u], bc[u]);
            v.w = fmaf(f23.y - tc[u], wc[u], bc[u]);
            *reinterpret_cast<float4*>(op + (size_t)(4 * ty + u) * HWL) = v;
        }
        __syncthreads();
    }
}

// =============================================================================
extern "C" void kernel_launch(void* const* d_in, const int* in_sizes, int n_in,
                              void* d_out, int out_size) {
    const float* x     = (const float*)d_in[0];
    const float* vinit = (const float*)d_in[1];
    const float* wgt   = (const float*)d_in[2];
    const float* bia   = (const float*)d_in[3];
    float* out = (float*)d_out;
    (void)in_sizes; (void)n_in; (void)out_size;

    cudaFuncSetAttribute(k_apply, cudaFuncAttributeMaxDynamicSharedMemorySize, AP_SMEM_BYTES);

    k_cov_partial<<<dim3(4, 32, 8), 256>>>(x);
    k_mean<<<8, 64>>>();
    k_cov_finalize<<<dim3(16, 8), 256>>>();
    k_pi<<<8, 64>>>(vinit);
    k_prep<<<8, 256>>>();
    k_apply<<<dim3(7, 32, 8), 256, AP_SMEM_BYTES>>>(x, wgt, bia, out);
}

// round 4
// speedup vs baseline: 1.0545x; 1.0545x over previous
#include <cuda_runtime.h>
#include <cuda_bf16.h>

// Problem constants
#define NN   32
#define CC   512
#define HWL  3136        // 56*56
#define GG   8
#define LL   64
#define MTOT 100352      // NN*HWL
#define EPSV 1e-4f
#define NPART 128        // 32 n-chunks * 4 k-chunks

// ---------------- scratch (device globals; no allocation allowed) -------------
__device__ float g_pcov[GG][NPART][LL * LL];  // partial Grams (16.8 MB)
__device__ float g_psum[GG][NPART][LL];       // partial channel sums
__device__ float g_mu[CC];
__device__ float g_cov[GG * LL * LL];
__device__ float g_subT[GG * LL * LL];        // whitening subspace, TRANSPOSED [g][j][i]
__device__ float g_t[CC];                     // t[c] = sum_j S[c][j] * mu[g*64+j]

// =============================================================================
// Kernel 1: partial Gram + partial channel sums.
// grid (4 k-chunks, 32 n, 8 g), 160 threads (5 warps; 136 compute the
// triangular 4x4 tile grid -> 85% FMA-feed vs 53% with 256 threads).
// =============================================================================
__global__ __launch_bounds__(160) void k_cov_partial(const float* __restrict__ x) {
    const int q = blockIdx.x;           // k-chunk 0..3
    const int n = blockIdx.y;
    const int g = blockIdx.z;
    __shared__ float4 Xs[64][17];       // [channel][k4], padded to kill conflicts

    const int tid = threadIdx.x;

    // triangular tile map: tid < 136 -> (ty, tx) with tx >= ty, 16x16 tile grid
    int ty = -1, tx = -1;
    if (tid < 136) {
        int t = tid, r = 0;
        while (t >= 16 - r) { t -= 16 - r; ++r; }
        ty = r; tx = r + t;
    }

    const int tiles = (q == 0) ? 13 : 12;
    const int k0    = (q == 0) ? 0 : (832 + (q - 1) * 768);
    const float* base = x + ((size_t)n * CC + (size_t)g * LL) * HWL + k0;

    float acc[4][4] = {};
    float rowsum = 0.f;

    for (int tI = 0; tI < tiles; ++tI) {
        __syncthreads();
        // load 64 rows x 16 float4 (each row contiguous in gmem)
        #pragma unroll
        for (int idx = tid; idx < 1024; idx += 160) {
            int r = idx >> 4, c = idx & 15;
            Xs[r][c] = *reinterpret_cast<const float4*>(base + (size_t)r * HWL + tI * 64 + c * 4);
        }
        __syncthreads();

        if (tid < 64) {
            #pragma unroll
            for (int c = 0; c < 16; ++c) {
                float4 v = Xs[tid][c];
                rowsum += v.x + v.y + v.z + v.w;
            }
        }
        if (tid < 136) {
            #pragma unroll
            for (int c = 0; c < 16; ++c) {
                float4 a[4], b[4];
                #pragma unroll
                for (int u = 0; u < 4; ++u) a[u] = Xs[4 * ty + u][c];
                #pragma unroll
                for (int u = 0; u < 4; ++u) b[u] = Xs[4 * tx + u][c];
                #pragma unroll
                for (int u = 0; u < 4; ++u)
                    #pragma unroll
                    for (int w = 0; w < 4; ++w)
                        acc[u][w] = fmaf(a[u].x, b[w].x,
                                    fmaf(a[u].y, b[w].y,
                                    fmaf(a[u].z, b[w].z,
                                    fmaf(a[u].w, b[w].w, acc[u][w]))));
            }
        }
    }

    const int p = n * 4 + q;
    if (tid < 64) g_psum[g][p][tid] = rowsum;
    if (tid < 136) {
        float* out = &g_pcov[g][p][0];
        #pragma unroll
        for (int u = 0; u < 4; ++u)
            #pragma unroll
            for (int w = 0; w < 4; ++w) {
                int i = 4 * ty + u, j = 4 * tx + w;
                out[i * 64 + j] = acc[u][w];
                if (ty != tx) out[j * 64 + i] = acc[u][w];
            }
    }
}

// =============================================================================
// Kernel 2a: reduce channel sums -> mu.  grid 8, 64 threads.
// =============================================================================
__global__ __launch_bounds__(64) void k_mean() {
    const int g = blockIdx.x, i = threadIdx.x;
    float s = 0.f;
    #pragma unroll 4
    for (int p = 0; p < NPART; ++p) s += g_psum[g][p][i];
    g_mu[g * LL + i] = s / (float)MTOT;
}

// =============================================================================
// Kernel 2b: reduce partial Grams -> cov (with -mu mu^T + eps I). grid (16,8).
// =============================================================================
__global__ __launch_bounds__(256) void k_cov_finalize() {
    const int g = blockIdx.y;
    const int e = blockIdx.x * 256 + threadIdx.x;     // 0..4095
    const int i = e >> 6, j = e & 63;
    float s0 = 0.f, s1 = 0.f, s2 = 0.f, s3 = 0.f;
    #pragma unroll 4
    for (int p = 0; p < NPART; p += 4) {
        s0 += g_pcov[g][p + 0][e];
        s1 += g_pcov[g][p + 1][e];
        s2 += g_pcov[g][p + 2][e];
        s3 += g_pcov[g][p + 3][e];
    }
    float c = ((s0 + s1) + (s2 + s3)) / (float)MTOT - g_mu[g * LL + i] * g_mu[g * LL + j];
    if (i == j) c += EPSV;
    g_cov[g * LL * LL + e] = c;
}

// =============================================================================
// Kernel 3: power iteration + deflation (unchanged — matched reference in R1).
// =============================================================================
#define MATVEC64(res, Aarr, vptr) {                                        \
    float y0 = 0.f, y1 = 0.f, y2 = 0.f, y3 = 0.f;                          \
    _Pragma("unroll")                                                      \
    for (int j_ = 0; j_ < 64; j_ += 4) {                                   \
        y0 = fmaf(Aarr[j_ + 0], (vptr)[j_ + 0], y0);                       \
        y1 = fmaf(Aarr[j_ + 1], (vptr)[j_ + 1], y1);                       \
        y2 = fmaf(Aarr[j_ + 2], (vptr)[j_ + 2], y2);                       \
        y3 = fmaf(Aarr[j_ + 3], (vptr)[j_ + 3], y3);                       \
    }                                                                      \
    res = (y0 + y1) + (y2 + y3);                                           \
}

__device__ __forceinline__ float sumsq64(const float* v) {
    float y0 = 0.f, y1 = 0.f, y2 = 0.f, y3 = 0.f;
    #pragma unroll
    for (int j = 0; j < 64; j += 4) {
        y0 = fmaf(v[j + 0], v[j + 0], y0);
        y1 = fmaf(v[j + 1], v[j + 1], y1);
        y2 = fmaf(v[j + 2], v[j + 2], y2);
        y3 = fmaf(v[j + 3], v[j + 3], y3);
    }
    return (y0 + y1) + (y2 + y3);
}
__device__ __forceinline__ float dot64(const float* a, const float* b) {
    float y0 = 0.f, y1 = 0.f, y2 = 0.f, y3 = 0.f;
    #pragma unroll
    for (int j = 0; j < 64; j += 4) {
        y0 = fmaf(a[j + 0], b[j + 0], y0);
        y1 = fmaf(a[j + 1], b[j + 1], y1);
        y2 = fmaf(a[j + 2], b[j + 2], y2);
        y3 = fmaf(a[j + 3], b[j + 3], y3);
    }
    return (y0 + y1) + (y2 + y3);
}

__global__ __launch_bounds__(64) void k_pi(const float* __restrict__ vinit) {
    const int g = blockIdx.x, i = threadIdx.x;
    __shared__ float vs[2][64];
    __shared__ float av[64];

    float A[64], S[64];
    #pragma unroll
    for (int j = 0; j < 64; ++j) {
        A[j] = g_cov[g * LL * LL + i * 64 + j];
        S[j] = 0.f;
    }

    float lam_prev = 0.f;

    for (int e = 0; e < 64; ++e) {
        __syncthreads();                                   // protect vs from prior step readers
        vs[0][i] = vinit[((size_t)g * LL + e) * LL + i];   // raw v0 (row e)
        __syncthreads();

        float n2  = sumsq64(vs[0]);
        float inv = 1.f / (sqrtf(n2) + 1e-12f);            // normalization of v0, folded in
        int cur = 0;

        #pragma unroll 1
        for (int it = 0; it < 19; ++it) {
            float y;
            MATVEC64(y, A, vs[cur]);
            y *= inv;                                      // apply previous step's normalization
            vs[cur ^ 1][i] = y;
            __syncthreads();
            cur ^= 1;
            n2  = sumsq64(vs[cur]);
            inv = 1.f / (sqrtf(n2) + 1e-12f);
        }

        // final normalized v
        float vi = vs[cur][i] * inv;
        __syncthreads();
        vs[cur ^ 1][i] = vi;
        __syncthreads();
        cur ^= 1;

        float Avi;
        MATVEC64(Avi, A, vs[cur]);
        av[i] = Avi;
        __syncthreads();

        float vAv = dot64(vs[cur], av);
        float vv  = sumsq64(vs[cur]);
        float lam = vAv / vv;

        if (e > 0 && (lam_prev < lam || lam < EPSV)) break;  // uniform across block

        float svi = rsqrtf(lam) * vi;
        #pragma unroll
        for (int j = 0; j < 64; ++j) {
            float vj = vs[cur][j];
            S[j] = fmaf(svi, vj, S[j]);     // subspace += rsqrt(lam) * v v^T
            A[j] = fmaf(-Avi, vj, A[j]);    // A -= (A v) v^T
        }
        lam_prev = lam;
    }

    // store subspace transposed: g_subT[g][j][i] = S[i][j]
    #pragma unroll
    for (int j = 0; j < 64; ++j) g_subT[g * LL * LL + j * 64 + i] = S[j];

    // t[i] = sum_j S[i][j] * mu[g*64+j]
    float t = 0.f;
    #pragma unroll
    for (int j = 0; j < 64; ++j) t = fmaf(S[j], g_mu[g * LL + j], t);
    g_t[g * LL + i] = t;
}

// =============================================================================
// Kernel 4: apply whitening + affine.  out = (S @ x - t) * weight + bias.
// grid (49 hw-tiles, 32 n, 8 g), 256 threads, 64x64 output tile, K=64.
// (R1 version — ~90% of FFMA roofline.)
// =============================================================================
__global__ __launch_bounds__(256) void k_apply(const float* __restrict__ x,
                                               const float* __restrict__ wgt,
                                               const float* __restrict__ bia,
                                               float* __restrict__ out) {
    const int hb = blockIdx.x;   // hw tile (64 wide), 49 exact
    const int n  = blockIdx.y;
    const int g  = blockIdx.z;

    __shared__ float4 Xt[64][17];   // [j][m4]  x tile
    __shared__ float4 St[64][17];   // [k][i4]  S^T tile

    const int tid = threadIdx.x;
    const int ty = tid >> 4, tx = tid & 15;

    // load S^T (already stored transposed -> coalesced float4 loads)
    const float* subT = g_subT + g * LL * LL;
    #pragma unroll
    for (int idx = tid; idx < 1024; idx += 256) {
        int j = idx >> 4, i4 = idx & 15;
        St[j][i4] = *reinterpret_cast<const float4*>(subT + j * 64 + i4 * 4);
    }
    // load x tile: 64 channels x 64 hw
    const float* base = x + ((size_t)n * CC + (size_t)g * LL) * HWL + hb * 64;
    #pragma unroll
    for (int idx = tid; idx < 1024; idx += 256) {
        int j = idx >> 4, m4 = idx & 15;
        Xt[j][m4] = *reinterpret_cast<const float4*>(base + (size_t)j * HWL + m4 * 4);
    }
    __syncthreads();

    float acc[4][4] = {};
    #pragma unroll
    for (int k = 0; k < 64; ++k) {
        float4 a = St[k][ty];   // S[4ty..4ty+3][k]
        float4 b = Xt[k][tx];   // X[k][4tx..4tx+3]
        acc[0][0] = fmaf(a.x, b.x, acc[0][0]);
        acc[0][1] = fmaf(a.x, b.y, acc[0][1]);
        acc[0][2] = fmaf(a.x, b.z, acc[0][2]);
        acc[0][3] = fmaf(a.x, b.w, acc[0][3]);
        acc[1][0] = fmaf(a.y, b.x, acc[1][0]);
        acc[1][1] = fmaf(a.y, b.y, acc[1][1]);
        acc[1][2] = fmaf(a.y, b.z, acc[1][2]);
        acc[1][3] = fmaf(a.y, b.w, acc[1][3]);
        acc[2][0] = fmaf(a.z, b.x, acc[2][0]);
        acc[2][1] = fmaf(a.z, b.y, acc[2][1]);
        acc[2][2] = fmaf(a.z, b.z, acc[2][2]);
        acc[2][3] = fmaf(a.z, b.w, acc[2][3]);
        acc[3][0] = fmaf(a.w, b.x, acc[3][0]);
        acc[3][1] = fmaf(a.w, b.y, acc[3][1]);
        acc[3][2] = fmaf(a.w, b.z, acc[3][2]);
        acc[3][3] = fmaf(a.w, b.w, acc[3][3]);
    }

    // epilogue: (acc - t) * w + b, vectorized stores
    #pragma unroll
    for (int u = 0; u < 4; ++u) {
        int c = g * LL + 4 * ty + u;
        float tt = g_t[c], ww = wgt[c], bb = bia[c];
        float4 r;
        r.x = fmaf(acc[u][0] - tt, ww, bb);
        r.y = fmaf(acc[u][1] - tt, ww, bb);
        r.z = fmaf(acc[u][2] - tt, ww, bb);
        r.w = fmaf(acc[u][3] - tt, ww, bb);
        *reinterpret_cast<float4*>(out + ((size_t)n * CC + c) * HWL + hb * 64 + 4 * tx) = r;
    }
}

// =============================================================================
extern "C" void kernel_launch(void* const* d_in, const int* in_sizes, int n_in,
                              void* d_out, int out_size) {
    const float* x     = (const float*)d_in[0];
    const float* vinit = (const float*)d_in[1];
    const float* wgt   = (const float*)d_in[2];
    const float* bia   = (const float*)d_in[3];
    float* out = (float*)d_out;
    (void)in_sizes; (void)n_in; (void)out_size;

    k_cov_partial<<<dim3(4, 32, 8), 160>>>(x);
    k_mean<<<8, 64>>>();
    k_cov_finalize<<<dim3(16, 8), 256>>>();
    k_pi<<<8, 64>>>(vinit);
    k_apply<<<dim3(49, 32, 8), 256>>>(x, wgt, bia, out);
}

// round 5
// speedup vs baseline: 1.1714x; 1.1108x over previous
#include <cuda_runtime.h>
#include <cuda_bf16.h>
#include <cstdint>

// Problem constants
#define NN   32
#define CC   512
#define HWL  3136        // 56*56
#define GG   8
#define LL   64
#define MTOT 100352      // NN*HWL
#define EPSV 1e-4f
#define NPART 128        // 32 n-chunks * 4 k-chunks

#define PADW 68          // floats per smem row (64 + 4 spread)
#define OPOS(o) (8*(o) + 4*((o)>>2))   // word offset of channel-octet o in a row

// ---------------- scratch (device globals; no allocation allowed) -------------
__device__ float g_pcov[GG][NPART][LL * LL];  // partial Grams
__device__ float g_psum[GG][NPART][LL];       // partial channel sums
__device__ float g_mu[CC];
__device__ float g_cov[GG * LL * LL];
__device__ float g_subT[GG * LL * LL];        // whitening subspace, TRANSPOSED [g][j][i]
__device__ float g_t[CC];                     // t[c] = sum_j S[c][j] * mu[g*64+j]

// ---------------- cp.async helpers -------------------------------------------
__device__ __forceinline__ uint32_t smem_u32(const void* p) {
    uint32_t a;
    asm("{ .reg .u64 t; cvta.to.shared.u64 t, %1; cvt.u32.u64 %0, t; }" : "=r"(a) : "l"(p));
    return a;
}
__device__ __forceinline__ void cpasync16(uint32_t dst, const void* src) {
    asm volatile("cp.async.ca.shared.global [%0], [%1], 16;" :: "r"(dst), "l"(src) : "memory");
}
#define CP_COMMIT() asm volatile("cp.async.commit_group;" ::: "memory")
#define CP_WAIT1()  asm volatile("cp.async.wait_group 1;" ::: "memory")
#define CP_WAIT0()  asm volatile("cp.async.wait_group 0;" ::: "memory")

// =============================================================================
// Kernel 1: partial Gram + partial channel sums.
// grid (4 k-chunks, 32 n, 8 g), 64 threads. 8x8 register tiles on the
// triangular 8x8 tile grid (36 active compute threads; all 64 load + rowsum).
// Smem layout: Xs[k][PADW] scalar, channel-octet rotated by k -> conflict-free
// compute loads, 50% crossbar load vs FMA-matched.
// =============================================================================
__global__ __launch_bounds__(64) void k_cov_partial(const float* __restrict__ x) {
    const int q = blockIdx.x;           // k-chunk 0..3
    const int n = blockIdx.y;
    const int g = blockIdx.z;
    __shared__ __align__(16) float Xs[64 * PADW];

    const int tid = threadIdx.x;

    // triangular tile map over 8x8 grid: tid < 36 -> (ty, tx), tx >= ty
    int ty = -1, tx = -1;
    if (tid < 36) {
        int t = tid, r = 0;
        while (t >= 8 - r) { t -= 8 - r; ++r; }
        ty = r; tx = r + t;
    }

    const int tiles = (q == 0) ? 13 : 12;
    const int k0    = (q == 0) ? 0 : (832 + (q - 1) * 768);
    const float* base = x + ((size_t)n * CC + (size_t)g * LL) * HWL + k0;

    float acc[8][8] = {};
    float rowsum = 0.f;
    const int ro = tid >> 3, rr = tid & 7;   // rowsum channel octet/slot

    for (int tI = 0; tI < tiles; ++tI) {
        __syncthreads();
        // load 64 ch x 64 hw, transpose into Xs[k][*] with octet rotation
        #pragma unroll
        for (int idx = tid; idx < 1024; idx += 64) {
            int r = idx >> 4, c = idx & 15;     // channel r, hw-f4 c
            float4 v = *reinterpret_cast<const float4*>(base + (size_t)r * HWL + tI * 64 + c * 4);
            int o = r >> 3, r7 = r & 7;
            int kb = 4 * c;
            float vv[4] = {v.x, v.y, v.z, v.w};
            #pragma unroll
            for (int i = 0; i < 4; ++i) {
                int k = kb + i;
                int op = (o + k) & 7;
                Xs[k * PADW + OPOS(op) + r7] = vv[i];
            }
        }
        __syncthreads();

        // rowsum for channel tid
        #pragma unroll 8
        for (int k = 0; k < 64; ++k) {
            int op = (ro + k) & 7;
            rowsum += Xs[k * PADW + OPOS(op) + rr];
        }

        if (tid < 36) {
            #pragma unroll 8
            for (int k = 0; k < 64; ++k) {
                int oa = (ty + k) & 7, ob = (tx + k) & 7;
                const float* ap = &Xs[k * PADW + OPOS(oa)];
                const float* bp = &Xs[k * PADW + OPOS(ob)];
                float a[8], b[8];
                *reinterpret_cast<float4*>(&a[0]) = *reinterpret_cast<const float4*>(ap);
                *reinterpret_cast<float4*>(&a[4]) = *reinterpret_cast<const float4*>(ap + 4);
                *reinterpret_cast<float4*>(&b[0]) = *reinterpret_cast<const float4*>(bp);
                *reinterpret_cast<float4*>(&b[4]) = *reinterpret_cast<const float4*>(bp + 4);
                #pragma unroll
                for (int u = 0; u < 8; ++u)
                    #pragma unroll
                    for (int w = 0; w < 8; ++w)
                        acc[u][w] = fmaf(a[u], b[w], acc[u][w]);
            }
        }
    }

    const int p = n * 4 + q;
    g_psum[g][p][tid] = rowsum;
    if (tid < 36) {
        float* outp = &g_pcov[g][p][0];
        #pragma unroll
        for (int u = 0; u < 8; ++u)
            #pragma unroll
            for (int w = 0; w < 8; ++w) {
                int i = 8 * ty + u, j = 8 * tx + w;
                outp[i * 64 + j] = acc[u][w];
                if (ty != tx) outp[j * 64 + i] = acc[u][w];
            }
    }
}

// =============================================================================
// Kernel 2a: reduce channel sums -> mu.  grid 8, 64 threads.
// =============================================================================
__global__ __launch_bounds__(64) void k_mean() {
    const int g = blockIdx.x, i = threadIdx.x;
    float s = 0.f;
    #pragma unroll 4
    for (int p = 0; p < NPART; ++p) s += g_psum[g][p][i];
    g_mu[g * LL + i] = s / (float)MTOT;
}

// =============================================================================
// Kernel 2b: reduce partial Grams -> cov (with -mu mu^T + eps I). grid (16,8).
// =============================================================================
__global__ __launch_bounds__(256) void k_cov_finalize() {
    const int g = blockIdx.y;
    const int e = blockIdx.x * 256 + threadIdx.x;
    const int i = e >> 6, j = e & 63;
    float s0 = 0.f, s1 = 0.f, s2 = 0.f, s3 = 0.f;
    #pragma unroll 4
    for (int p = 0; p < NPART; p += 4) {
        s0 += g_pcov[g][p + 0][e];
        s1 += g_pcov[g][p + 1][e];
        s2 += g_pcov[g][p + 2][e];
        s3 += g_pcov[g][p + 3][e];
    }
    float c = ((s0 + s1) + (s2 + s3)) / (float)MTOT - g_mu[g * LL + i] * g_mu[g * LL + j];
    if (i == j) c += EPSV;
    g_cov[g * LL * LL + e] = c;
}

// =============================================================================
// Kernel 3: power iteration + deflation (unchanged — matched reference in R1).
// =============================================================================
#define MATVEC64(res, Aarr, vptr) {                                        \
    float y0 = 0.f, y1 = 0.f, y2 = 0.f, y3 = 0.f;                          \
    _Pragma("unroll")                                                      \
    for (int j_ = 0; j_ < 64; j_ += 4) {                                   \
        y0 = fmaf(Aarr[j_ + 0], (vptr)[j_ + 0], y0);                       \
        y1 = fmaf(Aarr[j_ + 1], (vptr)[j_ + 1], y1);                       \
        y2 = fmaf(Aarr[j_ + 2], (vptr)[j_ + 2], y2);                       \
        y3 = fmaf(Aarr[j_ + 3], (vptr)[j_ + 3], y3);                       \
    }                                                                      \
    res = (y0 + y1) + (y2 + y3);                                           \
}

__device__ __forceinline__ float sumsq64(const float* v) {
    float y0 = 0.f, y1 = 0.f, y2 = 0.f, y3 = 0.f;
    #pragma unroll
    for (int j = 0; j < 64; j += 4) {
        y0 = fmaf(v[j + 0], v[j + 0], y0);
        y1 = fmaf(v[j + 1], v[j + 1], y1);
        y2 = fmaf(v[j + 2], v[j + 2], y2);
        y3 = fmaf(v[j + 3], v[j + 3], y3);
    }
    return (y0 + y1) + (y2 + y3);
}
__device__ __forceinline__ float dot64(const float* a, const float* b) {
    float y0 = 0.f, y1 = 0.f, y2 = 0.f, y3 = 0.f;
    #pragma unroll
    for (int j = 0; j < 64; j += 4) {
        y0 = fmaf(a[j + 0], b[j + 0], y0);
        y1 = fmaf(a[j + 1], b[j + 1], y1);
        y2 = fmaf(a[j + 2], b[j + 2], y2);
        y3 = fmaf(a[j + 3], b[j + 3], y3);
    }
    return (y0 + y1) + (y2 + y3);
}

__global__ __launch_bounds__(64) void k_pi(const float* __restrict__ vinit) {
    const int g = blockIdx.x, i = threadIdx.x;
    __shared__ float vs[2][64];
    __shared__ float av[64];

    float A[64], S[64];
    #pragma unroll
    for (int j = 0; j < 64; ++j) {
        A[j] = g_cov[g * LL * LL + i * 64 + j];
        S[j] = 0.f;
    }

    float lam_prev = 0.f;

    for (int e = 0; e < 64; ++e) {
        __syncthreads();
        vs[0][i] = vinit[((size_t)g * LL + e) * LL + i];
        __syncthreads();

        float n2  = sumsq64(vs[0]);
        float inv = 1.f / (sqrtf(n2) + 1e-12f);
        int cur = 0;

        #pragma unroll 1
        for (int it = 0; it < 19; ++it) {
            float y;
            MATVEC64(y, A, vs[cur]);
            y *= inv;
            vs[cur ^ 1][i] = y;
            __syncthreads();
            cur ^= 1;
            n2  = sumsq64(vs[cur]);
            inv = 1.f / (sqrtf(n2) + 1e-12f);
        }

        float vi = vs[cur][i] * inv;
        __syncthreads();
        vs[cur ^ 1][i] = vi;
        __syncthreads();
        cur ^= 1;

        float Avi;
        MATVEC64(Avi, A, vs[cur]);
        av[i] = Avi;
        __syncthreads();

        float vAv = dot64(vs[cur], av);
        float vv  = sumsq64(vs[cur]);
        float lam = vAv / vv;

        if (e > 0 && (lam_prev < lam || lam < EPSV)) break;

        float svi = rsqrtf(lam) * vi;
        #pragma unroll
        for (int j = 0; j < 64; ++j) {
            float vj = vs[cur][j];
            S[j] = fmaf(svi, vj, S[j]);
            A[j] = fmaf(-Avi, vj, A[j]);
        }
        lam_prev = lam;
    }

    #pragma unroll
    for (int j = 0; j < 64; ++j) g_subT[g * LL * LL + j * 64 + i] = S[j];

    float t = 0.f;
    #pragma unroll
    for (int j = 0; j < 64; ++j) t = fmaf(S[j], g_mu[g * LL + j], t);
    g_t[g * LL + i] = t;
}

// =============================================================================
// Kernel 4: apply whitening + affine.  out = (S @ x - t) * weight + bias.
// grid (7 hw-chunks, 32 n, 8 g), 64 threads, 8x8 register tiles.
// S loaded once per block into quad-spread smem; X tiles (64ch x 64hw)
// double-buffered via cp.async. Dynamic smem = 3 * 64*PADW floats.
// =============================================================================
#define AP_SMEM_BYTES (3 * 64 * PADW * 4)

__global__ __launch_bounds__(64) void k_apply(const float* __restrict__ x,
                                              const float* __restrict__ wgt,
                                              const float* __restrict__ bia,
                                              float* __restrict__ out) {
    extern __shared__ __align__(16) float smem[];
    float* Ss  = smem;                    // [64][PADW]
    float* Xb0 = smem + 64 * PADW;
    float* Xb1 = smem + 2 * 64 * PADW;

    const int hb = blockIdx.x;            // 0..6 (448 hw each)
    const int n  = blockIdx.y;
    const int g  = blockIdx.z;
    const int tid = threadIdx.x, ty = tid >> 3, tx = tid & 7;

    // load S^T rows (g_subT[g][j][i] = S[i][j] -> row j is the per-k row)
    const float* subT = g_subT + g * 4096;
    #pragma unroll
    for (int idx = tid; idx < 1024; idx += 64) {
        int j = idx >> 4, i4 = idx & 15;
        float4 v = *reinterpret_cast<const float4*>(subT + j * 64 + i4 * 4);
        *reinterpret_cast<float4*>(&Ss[j * PADW + 4 * (i4 + (i4 >> 3))]) = v;
    }

    const float* xbase = x   + ((size_t)n * CC + (size_t)g * LL) * HWL + hb * 448;
    float*       obase = out + ((size_t)n * CC + (size_t)g * LL) * HWL + hb * 448;

    // epilogue constants (8 channels per thread)
    float tc[8], wc[8], bc[8];
    #pragma unroll
    for (int u = 0; u < 8; ++u) {
        int c = g * LL + 8 * ty + u;
        tc[u] = g_t[c]; wc[u] = wgt[c]; bc[u] = bia[c];
    }

    const uint32_t xs0 = smem_u32(Xb0), xs1 = smem_u32(Xb1);

    // issue tile t into buffer
    #define ISSUE(dst, t) do {                                                          \
        _Pragma("unroll")                                                               \
        for (int idx = tid; idx < 1024; idx += 64) {                                    \
            int r = idx >> 4, c = idx & 15;                                             \
            cpasync16((dst) + (uint32_t)(r * PADW + 4 * (c + (c >> 3))) * 4,            \
                      xbase + (size_t)r * HWL + (t) * 64 + c * 4);                      \
        }                                                                               \
        CP_COMMIT();                                                                    \
    } while (0)

    ISSUE(xs0, 0);

    for (int t = 0; t < 7; ++t) {
        if (t < 6) { ISSUE((t & 1) ? xs0 : xs1, t + 1); CP_WAIT1(); }
        else       { CP_WAIT0(); }
        __syncthreads();

        const float* Xc = (t & 1) ? Xb1 : Xb0;
        float acc[8][8] = {};
        #pragma unroll 8
        for (int k = 0; k < 64; ++k) {
            float a[8], b[8];
            const float* ap = &Ss[k * PADW + OPOS(ty)];
            const float* bp = &Xc[k * PADW + OPOS(tx)];
            *reinterpret_cast<float4*>(&a[0]) = *reinterpret_cast<const float4*>(ap);
            *reinterpret_cast<float4*>(&a[4]) = *reinterpret_cast<const float4*>(ap + 4);
            *reinterpret_cast<float4*>(&b[0]) = *reinterpret_cast<const float4*>(bp);
            *reinterpret_cast<float4*>(&b[4]) = *reinterpret_cast<const float4*>(bp + 4);
            #pragma unroll
            for (int u = 0; u < 8; ++u)
                #pragma unroll
                for (int w = 0; w < 8; ++w)
                    acc[u][w] = fmaf(a[u], b[w], acc[u][w]);
        }

        // epilogue: (acc - t) * w + b
        float* op = obase + t * 64 + 8 * tx;
        #pragma unroll
        for (int u = 0; u < 8; ++u) {
            float4 v0, v1;
            v0.x = fmaf(acc[u][0] - tc[u], wc[u], bc[u]);
            v0.y = fmaf(acc[u][1] - tc[u], wc[u], bc[u]);
            v0.z = fmaf(acc[u][2] - tc[u], wc[u], bc[u]);
            v0.w = fmaf(acc[u][3] - tc[u], wc[u], bc[u]);
            v1.x = fmaf(acc[u][4] - tc[u], wc[u], bc[u]);
            v1.y = fmaf(acc[u][5] - tc[u], wc[u], bc[u]);
            v1.z = fmaf(acc[u][6] - tc[u], wc[u], bc[u]);
            v1.w = fmaf(acc[u][7] - tc[u], wc[u], bc[u]);
            *reinterpret_cast<float4*>(op + (size_t)(8 * ty + u) * HWL)     = v0;
            *reinterpret_cast<float4*>(op + (size_t)(8 * ty + u) * HWL + 4) = v1;
        }
        __syncthreads();
    }
    #undef ISSUE
}

// =============================================================================
extern "C" void kernel_launch(void* const* d_in, const int* in_sizes, int n_in,
                              void* d_out, int out_size) {
    const float* x     = (const float*)d_in[0];
    const float* vinit = (const float*)d_in[1];
    const float* wgt   = (const float*)d_in[2];
    const float* bia   = (const float*)d_in[3];
    float* out = (float*)d_out;
    (void)in_sizes; (void)n_in; (void)out_size;

    cudaFuncSetAttribute(k_apply, cudaFuncAttributeMaxDynamicSharedMemorySize, AP_SMEM_BYTES);

    k_cov_partial<<<dim3(4, 32, 8), 64>>>(x);
    k_mean<<<8, 64>>>();
    k_cov_finalize<<<dim3(16, 8), 256>>>();
    k_pi<<<8, 64>>>(vinit);
    k_apply<<<dim3(7, 32, 8), 64, AP_SMEM_BYTES>>>(x, wgt, bia, out);
}

// round 6
// speedup vs baseline: 1.3279x; 1.1337x over previous
#include <cuda_runtime.h>
#include <cuda_bf16.h>
#include <cstdint>

// Problem constants
#define NN   32
#define CC   512
#define HWL  3136        // 56*56
#define GG   8
#define LL   64
#define MTOT 100352      // NN*HWL
#define EPSV 1e-4f
#define NPART 128        // 32 n-chunks * 4 k-chunks

#define PADW 68          // floats per smem row (64 + 4 spread)
#define OPOS(o) (8*(o) + 4*((o)>>2))   // word offset of channel-octet o in a row

typedef unsigned long long ull;

// ---------------- scratch (device globals; no allocation allowed) -------------
__device__ float g_pcov[GG][NPART][LL * LL];  // partial Grams
__device__ float g_psum[GG][NPART][LL];       // partial channel sums
__device__ float g_mu[CC];
__device__ float g_cov[GG * LL * LL];
__device__ float g_subT[GG * LL * LL];        // whitening subspace, TRANSPOSED [g][j][i]
__device__ float g_t[CC];                     // t[c] = sum_j S[c][j] * mu[g*64+j]

// ---------------- helpers ------------------------------------------------------
__device__ __forceinline__ uint32_t smem_u32(const void* p) {
    uint32_t a;
    asm("{ .reg .u64 t; cvta.to.shared.u64 t, %1; cvt.u32.u64 %0, t; }" : "=r"(a) : "l"(p));
    return a;
}
__device__ __forceinline__ void cpasync16(uint32_t dst, const void* src) {
    asm volatile("cp.async.ca.shared.global [%0], [%1], 16;" :: "r"(dst), "l"(src) : "memory");
}
#define CP_COMMIT() asm volatile("cp.async.commit_group;" ::: "memory")
#define CP_WAIT1()  asm volatile("cp.async.wait_group 1;" ::: "memory")
#define CP_WAIT0()  asm volatile("cp.async.wait_group 0;" ::: "memory")

__device__ __forceinline__ ull ffma2(ull a, ull b, ull c) {
    ull d;
    asm("fma.rn.f32x2 %0, %1, %2, %3;" : "=l"(d) : "l"(a), "l"(b), "l"(c));
    return d;
}
__device__ __forceinline__ ull dup2(float v) {
    ull d;
    asm("mov.b64 %0, {%1, %1};" : "=l"(d) : "f"(v));
    return d;
}
__device__ __forceinline__ ull pack2(float lo, float hi) {
    ull d;
    asm("mov.b64 %0, {%1, %2};" : "=l"(d) : "f"(lo), "f"(hi));
    return d;
}
__device__ __forceinline__ float2 unpack2(ull v) {
    float lo, hi;
    asm("mov.b64 {%0, %1}, %2;" : "=f"(lo), "=f"(hi) : "l"(v));
    return make_float2(lo, hi);
}

// =============================================================================
// Kernel 1: partial Gram + partial channel sums, packed FFMA2.
// grid (4 k-chunks, 32 n, 8 g), 64 threads. Thread = 16 row-ch (8 f32x2 pairs)
// x 4 col-ch; block covers the full 64x64 Gram (no triangular masking — the
// issue stream is what matters). Smem: rotated-octet layout (R5, proven).
// =============================================================================
__global__ __launch_bounds__(64) void k_cov_partial(const float* __restrict__ x) {
    const int q = blockIdx.x;           // k-chunk 0..3
    const int n = blockIdx.y;
    const int g = blockIdx.z;
    __shared__ __align__(16) float Xs[64 * PADW];

    const int tid  = threadIdx.x;
    const int cg   = tid >> 4;          // row-group: 16 channels (8 pairs)
    const int colg = tid & 15;          // col-group: 4 channels

    const int tiles = (q == 0) ? 13 : 12;
    const int k0    = (q == 0) ? 0 : (832 + (q - 1) * 768);
    const float* base = x + ((size_t)n * CC + (size_t)g * LL) * HWL + k0;

    ull acc[8][4];
    #pragma unroll
    for (int p = 0; p < 8; ++p)
        #pragma unroll
        for (int w = 0; w < 4; ++w) acc[p][w] = 0ull;

    float rowsum = 0.f;
    const int ro = tid >> 3, rr = tid & 7;   // rowsum channel octet/slot
    const int bo = colg >> 1, bh = 4 * (colg & 1);

    for (int tI = 0; tI < tiles; ++tI) {
        __syncthreads();
        // load 64 ch x 64 hw, transpose into Xs[k][*] with octet rotation
        #pragma unroll
        for (int idx = tid; idx < 1024; idx += 64) {
            int r = idx >> 4, c = idx & 15;     // channel r, hw-f4 c
            float4 v = *reinterpret_cast<const float4*>(base + (size_t)r * HWL + tI * 64 + c * 4);
            int o = r >> 3, r7 = r & 7;
            float vv[4] = {v.x, v.y, v.z, v.w};
            #pragma unroll
            for (int i = 0; i < 4; ++i) {
                int k = 4 * c + i;
                int op = (o + k) & 7;
                Xs[k * PADW + OPOS(op) + r7] = vv[i];
            }
        }
        __syncthreads();

        #pragma unroll 8
        for (int k = 0; k < 64; ++k) {
            const float* row = &Xs[k * PADW];
            // rowsum for channel tid
            rowsum += row[OPOS((ro + k) & 7) + rr];

            // a: 16 row-channels = octets 2cg, 2cg+1 (rotated)
            int oa0 = (2 * cg + k) & 7, oa1 = (2 * cg + 1 + k) & 7;
            ull a2[8];
            {
                float4 v0 = *reinterpret_cast<const float4*>(row + OPOS(oa0));
                float4 v1 = *reinterpret_cast<const float4*>(row + OPOS(oa0) + 4);
                float4 v2 = *reinterpret_cast<const float4*>(row + OPOS(oa1));
                float4 v3 = *reinterpret_cast<const float4*>(row + OPOS(oa1) + 4);
                a2[0] = pack2(v0.x, v0.y); a2[1] = pack2(v0.z, v0.w);
                a2[2] = pack2(v1.x, v1.y); a2[3] = pack2(v1.z, v1.w);
                a2[4] = pack2(v2.x, v2.y); a2[5] = pack2(v2.z, v2.w);
                a2[6] = pack2(v3.x, v3.y); a2[7] = pack2(v3.z, v3.w);
            }
            // b: 4 col-channels, duplicated into both lanes
            float4 bv = *reinterpret_cast<const float4*>(row + OPOS((bo + k) & 7) + bh);
            ull bd0 = dup2(bv.x), bd1 = dup2(bv.y), bd2 = dup2(bv.z), bd3 = dup2(bv.w);

            #pragma unroll
            for (int p = 0; p < 8; ++p) {
                acc[p][0] = ffma2(a2[p], bd0, acc[p][0]);
                acc[p][1] = ffma2(a2[p], bd1, acc[p][1]);
                acc[p][2] = ffma2(a2[p], bd2, acc[p][2]);
                acc[p][3] = ffma2(a2[p], bd3, acc[p][3]);
            }
        }
    }

    const int p = n * 4 + q;
    g_psum[g][p][tid] = rowsum;
    float* outp = &g_pcov[g][p][0];
    #pragma unroll
    for (int pp = 0; pp < 8; ++pp) {
        float2 f0 = unpack2(acc[pp][0]);
        float2 f1 = unpack2(acc[pp][1]);
        float2 f2 = unpack2(acc[pp][2]);
        float2 f3 = unpack2(acc[pp][3]);
        int i0 = cg * 16 + 2 * pp;
        float4 lo4 = make_float4(f0.x, f1.x, f2.x, f3.x);
        float4 hi4 = make_float4(f0.y, f1.y, f2.y, f3.y);
        *reinterpret_cast<float4*>(outp + (size_t)i0 * 64 + colg * 4)       = lo4;
        *reinterpret_cast<float4*>(outp + (size_t)(i0 + 1) * 64 + colg * 4) = hi4;
    }
}

// =============================================================================
// Kernel 2a: reduce channel sums -> mu.  grid 8, 64 threads.
// =============================================================================
__global__ __launch_bounds__(64) void k_mean() {
    const int g = blockIdx.x, i = threadIdx.x;
    float s = 0.f;
    #pragma unroll 4
    for (int p = 0; p < NPART; ++p) s += g_psum[g][p][i];
    g_mu[g * LL + i] = s / (float)MTOT;
}

// =============================================================================
// Kernel 2b: reduce partial Grams -> cov (with -mu mu^T + eps I). grid (16,8).
// =============================================================================
__global__ __launch_bounds__(256) void k_cov_finalize() {
    const int g = blockIdx.y;
    const int e = blockIdx.x * 256 + threadIdx.x;
    const int i = e >> 6, j = e & 63;
    float s0 = 0.f, s1 = 0.f, s2 = 0.f, s3 = 0.f;
    #pragma unroll 4
    for (int p = 0; p < NPART; p += 4) {
        s0 += g_pcov[g][p + 0][e];
        s1 += g_pcov[g][p + 1][e];
        s2 += g_pcov[g][p + 2][e];
        s3 += g_pcov[g][p + 3][e];
    }
    float c = ((s0 + s1) + (s2 + s3)) / (float)MTOT - g_mu[g * LL + i] * g_mu[g * LL + j];
    if (i == j) c += EPSV;
    g_cov[g * LL * LL + e] = c;
}

// =============================================================================
// Kernel 3: power iteration + deflation (unchanged — matched reference in R1).
// =============================================================================
#define MATVEC64(res, Aarr, vptr) {                                        \
    float y0 = 0.f, y1 = 0.f, y2 = 0.f, y3 = 0.f;                          \
    _Pragma("unroll")                                                      \
    for (int j_ = 0; j_ < 64; j_ += 4) {                                   \
        y0 = fmaf(Aarr[j_ + 0], (vptr)[j_ + 0], y0);                       \
        y1 = fmaf(Aarr[j_ + 1], (vptr)[j_ + 1], y1);                       \
        y2 = fmaf(Aarr[j_ + 2], (vptr)[j_ + 2], y2);                       \
        y3 = fmaf(Aarr[j_ + 3], (vptr)[j_ + 3], y3);                       \
    }                                                                      \
    res = (y0 + y1) + (y2 + y3);                                           \
}

__device__ __forceinline__ float sumsq64(const float* v) {
    float y0 = 0.f, y1 = 0.f, y2 = 0.f, y3 = 0.f;
    #pragma unroll
    for (int j = 0; j < 64; j += 4) {
        y0 = fmaf(v[j + 0], v[j + 0], y0);
        y1 = fmaf(v[j + 1], v[j + 1], y1);
        y2 = fmaf(v[j + 2], v[j + 2], y2);
        y3 = fmaf(v[j + 3], v[j + 3], y3);
    }
    return (y0 + y1) + (y2 + y3);
}
__device__ __forceinline__ float dot64(const float* a, const float* b) {
    float y0 = 0.f, y1 = 0.f, y2 = 0.f, y3 = 0.f;
    #pragma unroll
    for (int j = 0; j < 64; j += 4) {
        y0 = fmaf(a[j + 0], b[j + 0], y0);
        y1 = fmaf(a[j + 1], b[j + 1], y1);
        y2 = fmaf(a[j + 2], b[j + 2], y2);
        y3 = fmaf(a[j + 3], b[j + 3], y3);
    }
    return (y0 + y1) + (y2 + y3);
}

__global__ __launch_bounds__(64) void k_pi(const float* __restrict__ vinit) {
    const int g = blockIdx.x, i = threadIdx.x;
    __shared__ float vs[2][64];
    __shared__ float av[64];

    float A[64], S[64];
    #pragma unroll
    for (int j = 0; j < 64; ++j) {
        A[j] = g_cov[g * LL * LL + i * 64 + j];
        S[j] = 0.f;
    }

    float lam_prev = 0.f;

    for (int e = 0; e < 64; ++e) {
        __syncthreads();
        vs[0][i] = vinit[((size_t)g * LL + e) * LL + i];
        __syncthreads();

        float n2  = sumsq64(vs[0]);
        float inv = 1.f / (sqrtf(n2) + 1e-12f);
        int cur = 0;

        #pragma unroll 1
        for (int it = 0; it < 19; ++it) {
            float y;
            MATVEC64(y, A, vs[cur]);
            y *= inv;
            vs[cur ^ 1][i] = y;
            __syncthreads();
            cur ^= 1;
            n2  = sumsq64(vs[cur]);
            inv = 1.f / (sqrtf(n2) + 1e-12f);
        }

        float vi = vs[cur][i] * inv;
        __syncthreads();
        vs[cur ^ 1][i] = vi;
        __syncthreads();
        cur ^= 1;

        float Avi;
        MATVEC64(Avi, A, vs[cur]);
        av[i] = Avi;
        __syncthreads();

        float vAv = dot64(vs[cur], av);
        float vv  = sumsq64(vs[cur]);
        float lam = vAv / vv;

        if (e > 0 && (lam_prev < lam || lam < EPSV)) break;

        float svi = rsqrtf(lam) * vi;
        #pragma unroll
        for (int j = 0; j < 64; ++j) {
            float vj = vs[cur][j];
            S[j] = fmaf(svi, vj, S[j]);
            A[j] = fmaf(-Avi, vj, A[j]);
        }
        lam_prev = lam;
    }

    #pragma unroll
    for (int j = 0; j < 64; ++j) g_subT[g * LL * LL + j * 64 + i] = S[j];

    float t = 0.f;
    #pragma unroll
    for (int j = 0; j < 64; ++j) t = fmaf(S[j], g_mu[g * LL + j], t);
    g_t[g * LL + i] = t;
}

// =============================================================================
// Kernel 4: apply whitening + affine, packed FFMA2.
// out = (S @ x) * w + (b - t*w).  grid (7 hw-chunks, 32 n, 8 g), 64 threads.
// Thread = 16 out-ch (8 pairs) x 4 hw; block covers 64x64 per tile, 7 tiles.
// S in octet-spread smem (loaded once); X double-buffered via cp.async.
// =============================================================================
#define AP_SMEM_BYTES (3 * 64 * PADW * 4)

__global__ __launch_bounds__(64) void k_apply(const float* __restrict__ x,
                                              const float* __restrict__ wgt,
                                              const float* __restrict__ bia,
                                              float* __restrict__ out) {
    extern __shared__ __align__(16) float smem[];
    float* Ss  = smem;                    // [64][PADW]
    float* Xb0 = smem + 64 * PADW;
    float* Xb1 = smem + 2 * 64 * PADW;

    const int hb = blockIdx.x;            // 0..6 (448 hw each)
    const int n  = blockIdx.y;
    const int g  = blockIdx.z;
    const int tid = threadIdx.x;
    const int cg  = tid >> 4;             // out-channel group (16 ch)
    const int hwg = tid & 15;             // hw group (4 hw)

    // load S^T rows into octet-spread layout (row j = k-index j)
    const float* subT = g_subT + g * 4096;
    #pragma unroll
    for (int idx = tid; idx < 1024; idx += 64) {
        int j = idx >> 4, c = idx & 15;   // c = float4 index (octet c>>1, half c&1)
        float4 v = *reinterpret_cast<const float4*>(subT + j * 64 + c * 4);
        *reinterpret_cast<float4*>(&Ss[j * PADW + OPOS(c >> 1) + 4 * (c & 1)]) = v;
    }

    const float* xbase = x   + ((size_t)n * CC + (size_t)g * LL) * HWL + hb * 448;
    float*       obase = out + ((size_t)n * CC + (size_t)g * LL) * HWL + hb * 448;

    // packed epilogue constants: out = acc * w + (b - t*w), per channel pair
    ull w2[8], q2[8];
    #pragma unroll
    for (int pp = 0; pp < 8; ++pp) {
        int c0 = g * LL + cg * 16 + 2 * pp;
        float wa = wgt[c0], wb = wgt[c0 + 1];
        float qa = bia[c0]     - g_t[c0]     * wa;
        float qb = bia[c0 + 1] - g_t[c0 + 1] * wb;
        w2[pp] = pack2(wa, wb);
        q2[pp] = pack2(qa, qb);
    }

    const uint32_t xs0 = smem_u32(Xb0), xs1 = smem_u32(Xb1);

    #define ISSUE(dst, t) do {                                                          \
        _Pragma("unroll")                                                               \
        for (int idx = tid; idx < 1024; idx += 64) {                                    \
            int r = idx >> 4, c = idx & 15;                                             \
            cpasync16((dst) + (uint32_t)(r * PADW + OPOS(c >> 1) + 4 * (c & 1)) * 4,    \
                      xbase + (size_t)r * HWL + (t) * 64 + c * 4);                      \
        }                                                                               \
        CP_COMMIT();                                                                    \
    } while (0)

    ISSUE(xs0, 0);

    const int bpos = OPOS(hwg >> 1) + 4 * (hwg & 1);
    const int apos0 = OPOS(2 * cg), apos1 = OPOS(2 * cg + 1);

    for (int t = 0; t < 7; ++t) {
        if (t < 6) { ISSUE((t & 1) ? xs0 : xs1, t + 1); CP_WAIT1(); }
        else       { CP_WAIT0(); }
        __syncthreads();

        const float* Xc = (t & 1) ? Xb1 : Xb0;
        ull acc[8][4];
        #pragma unroll
        for (int p = 0; p < 8; ++p)
            #pragma unroll
            for (int w = 0; w < 4; ++w) acc[p][w] = 0ull;

        #pragma unroll 8
        for (int k = 0; k < 64; ++k) {
            const float* srow = &Ss[k * PADW];
            const float* xrow = &Xc[k * PADW];
            ull a2[8];
            {
                float4 v0 = *reinterpret_cast<const float4*>(srow + apos0);
                float4 v1 = *reinterpret_cast<const float4*>(srow + apos0 + 4);
                float4 v2 = *reinterpret_cast<const float4*>(srow + apos1);
                float4 v3 = *reinterpret_cast<const float4*>(srow + apos1 + 4);
                a2[0] = pack2(v0.x, v0.y); a2[1] = pack2(v0.z, v0.w);
                a2[2] = pack2(v1.x, v1.y); a2[3] = pack2(v1.z, v1.w);
                a2[4] = pack2(v2.x, v2.y); a2[5] = pack2(v2.z, v2.w);
                a2[6] = pack2(v3.x, v3.y); a2[7] = pack2(v3.z, v3.w);
            }
            float4 bv = *reinterpret_cast<const float4*>(xrow + bpos);
            ull bd0 = dup2(bv.x), bd1 = dup2(bv.y), bd2 = dup2(bv.z), bd3 = dup2(bv.w);

            #pragma unroll
            for (int p = 0; p < 8; ++p) {
                acc[p][0] = ffma2(a2[p], bd0, acc[p][0]);
                acc[p][1] = ffma2(a2[p], bd1, acc[p][1]);
                acc[p][2] = ffma2(a2[p], bd2, acc[p][2]);
                acc[p][3] = ffma2(a2[p], bd3, acc[p][3]);
            }
        }

        // packed epilogue + store: out = acc * w + q
        float* op = obase + t * 64 + hwg * 4;
        #pragma unroll
        for (int pp = 0; pp < 8; ++pp) {
            ull r0 = ffma2(acc[pp][0], w2[pp], q2[pp]);
            ull r1 = ffma2(acc[pp][1], w2[pp], q2[pp]);
            ull r2 = ffma2(acc[pp][2], w2[pp], q2[pp]);
            ull r3 = ffma2(acc[pp][3], w2[pp], q2[pp]);
            float2 f0 = unpack2(r0), f1 = unpack2(r1), f2 = unpack2(r2), f3 = unpack2(r3);
            int c0 = cg * 16 + 2 * pp;
            float4 lo4 = make_float4(f0.x, f1.x, f2.x, f3.x);
            float4 hi4 = make_float4(f0.y, f1.y, f2.y, f3.y);
            *reinterpret_cast<float4*>(op + (size_t)c0 * HWL)       = lo4;
            *reinterpret_cast<float4*>(op + (size_t)(c0 + 1) * HWL) = hi4;
        }
        __syncthreads();
    }
    #undef ISSUE
}

// =============================================================================
extern "C" void kernel_launch(void* const* d_in, const int* in_sizes, int n_in,
                              void* d_out, int out_size) {
    const float* x     = (const float*)d_in[0];
    const float* vinit = (const float*)d_in[1];
    const float* wgt   = (const float*)d_in[2];
    const float* bia   = (const float*)d_in[3];
    float* out = (float*)d_out;
    (void)in_sizes; (void)n_in; (void)out_size;

    cudaFuncSetAttribute(k_apply, cudaFuncAttributeMaxDynamicSharedMemorySize, AP_SMEM_BYTES);

    k_cov_partial<<<dim3(4, 32, 8), 64>>>(x);
    k_mean<<<8, 64>>>();
    k_cov_finalize<<<dim3(16, 8), 256>>>();
    k_pi<<<8, 64>>>(vinit);
    k_apply<<<dim3(7, 32, 8), 64, AP_SMEM_BYTES>>>(x, wgt, bia, out);
}